// round 11
// baseline (speedup 1.0000x reference)
#include <cuda_runtime.h>

// inputs: [128, 65536, 3] f32 interleaved (x,y,z)
// output: [128, 65536, 2] f32: (-(clip(x,-1,1)+1)*90, atan2(z,y)*180/pi)
//
// psi = acos(y/sqrt(y^2+z^2)) with sign of z  ==  atan2(z, y)
//
// 8 points/thread via 256-bit (v8.b32) loads+stores: 3x LDG.256 in,
// 2x STG.256 out. Same MLP_p1=3 as the best 128-bit kernel but half the
// LSU issue slots and L1tex wavefronts per byte.

#define TPB 256

static __device__ __forceinline__ void ldg256(const float* p, float* v) {
    asm("ld.global.nc.v8.b32 {%0,%1,%2,%3,%4,%5,%6,%7}, [%8];"
        : "=f"(v[0]), "=f"(v[1]), "=f"(v[2]), "=f"(v[3]),
          "=f"(v[4]), "=f"(v[5]), "=f"(v[6]), "=f"(v[7])
        : "l"(p));
}

static __device__ __forceinline__ void stg256(float* p, const float* v) {
    asm volatile("st.global.v8.b32 [%0], {%1,%2,%3,%4,%5,%6,%7,%8};"
                 :: "l"(p),
                    "f"(v[0]), "f"(v[1]), "f"(v[2]), "f"(v[3]),
                    "f"(v[4]), "f"(v[5]), "f"(v[6]), "f"(v[7])
                 : "memory");
}

static __device__ __forceinline__ float fast_atan2_deg(float z, float y) {
    // atan2(z,y) * (180/pi), minimax atan poly on [0,1], max err ~1e-5 rad
    float ay = fabsf(y), az = fabsf(z);
    float mn = fminf(ay, az), mx = fmaxf(ay, az);
    float a = __fdividef(mn, mx);
    float s = a * a;
    float r = fmaf(fmaf(fmaf(fmaf(0.0208351f, s, -0.0851330f),
                             s, 0.1801410f),
                        s, -0.3302995f),
                   s, 0.9998660f) * a;
    if (az > ay) r = 1.5707963267948966f - r;
    if (y < 0.0f) r = 3.14159265358979323f - r;
    r = (z < 0.0f) ? -r : r;
    return r * 57.295779513082323f;
}

static __device__ __forceinline__ void point_op(float x, float y, float z,
                                                float& o0, float& o1) {
    float cx = fminf(fmaxf(x, -1.0f), 1.0f);
    o0 = fmaf(cx, -90.0f, -90.0f);   // -(cx+1)*90
    o1 = fast_atan2_deg(z, y);
}

__global__ void __launch_bounds__(TPB) cil_kernel(const float* __restrict__ in,
                                                  float* __restrict__ out,
                                                  int n_oct) {
    int t = blockIdx.x * TPB + threadIdx.x;
    if (t >= n_oct) return;

    // 8 points: 24 floats in (3x 32B), 16 floats out (2x 32B); both 32B-aligned
    const float* src = in + (size_t)t * 24;
    float v[24];
    ldg256(src +  0, v +  0);
    ldg256(src +  8, v +  8);
    ldg256(src + 16, v + 16);

    float q[16];
#pragma unroll
    for (int i = 0; i < 8; i++) {
        point_op(v[3 * i + 0], v[3 * i + 1], v[3 * i + 2],
                 q[2 * i + 0], q[2 * i + 1]);
    }

    float* dst = out + (size_t)t * 16;
    stg256(dst + 0, q + 0);
    stg256(dst + 8, q + 8);
}

extern "C" void kernel_launch(void* const* d_in, const int* in_sizes, int n_in,
                              void* d_out, int out_size) {
    const float* in = (const float*)d_in[0];
    float* out = (float*)d_out;

    int n_points = in_sizes[0] / 3;   // 8,388,608
    int n_oct = n_points / 8;         // 1,048,576 (exactly divisible)

    int blocks = (n_oct + TPB - 1) / TPB;   // 4096
    cil_kernel<<<blocks, TPB>>>(in, out, n_oct);
}